// round 2
// baseline (speedup 1.0000x reference)
#include <cuda_runtime.h>
#include <cuda_bf16.h>

// dense_image_warp: out[b,y,x,c] = bilinear(image, (y,x) - flow[b,y,x])
// B=8, H=256, W=256, C=64 (fp32).
// One thread per 8 channels (2x float4): 8 threads per pixel.
// 8 independent 128-bit gathers per thread for MLP; streaming stores.

__device__ __forceinline__ void stcs4(float4* p, float4 v) {
    asm volatile("st.global.cs.v4.f32 [%0], {%1,%2,%3,%4};"
                 :: "l"(p), "f"(v.x), "f"(v.y), "f"(v.z), "f"(v.w) : "memory");
}

__global__ __launch_bounds__(256) void warp_kernel(
    const float4* __restrict__ img,    // [B,H,W,C] as float4, pixel stride 16
    const float2* __restrict__ flow,   // [B,H,W,2] as float2, one per pixel
    float4* __restrict__ out)
{
    const int tid = blockIdx.x * blockDim.x + threadIdx.x;
    const int c8 = tid & 7;           // channel-octet 0..7 (8 channels each)
    const int p  = tid >> 3;          // pixel index: b*65536 + y*256 + x
    const int x  = p & 255;
    const int y  = (p >> 8) & 255;
    const int b  = p >> 16;

    const float2 f = __ldg(&flow[p]);
    const float qy = (float)y - f.x;
    const float qx = (float)x - f.y;

    float fy = floorf(qy); fy = fminf(fmaxf(fy, 0.0f), 254.0f);
    float fx = floorf(qx); fx = fminf(fmaxf(fx, 0.0f), 254.0f);
    const float ay = fminf(fmaxf(qy - fy, 0.0f), 1.0f);
    const float ax = fminf(fmaxf(qx - fx, 0.0f), 1.0f);

    const int iy = (int)fy;
    const int ix = (int)fx;

    // base in float4 units: (((b*256 + iy)*256 + ix) * 64 + c8*8) / 4
    const long base = (((long)((b << 8) + iy) << 8) + ix) * 16 + (c8 << 1);
    const float4* g = img + base;

    // 8 independent 128-bit gathers — all issued before any dependent math
    const float4 tl0 = __ldg(g);
    const float4 tl1 = __ldg(g + 1);
    const float4 tr0 = __ldg(g + 16);
    const float4 tr1 = __ldg(g + 17);
    const float4 bl0 = __ldg(g + 16 * 256);
    const float4 bl1 = __ldg(g + 16 * 256 + 1);
    const float4 br0 = __ldg(g + 16 * 256 + 16);
    const float4 br1 = __ldg(g + 16 * 256 + 17);

    float4 r0, r1;
    {
        float top, bot;
        top = fmaf(ax, tr0.x - tl0.x, tl0.x);
        bot = fmaf(ax, br0.x - bl0.x, bl0.x);
        r0.x = fmaf(ay, bot - top, top);
        top = fmaf(ax, tr0.y - tl0.y, tl0.y);
        bot = fmaf(ax, br0.y - bl0.y, bl0.y);
        r0.y = fmaf(ay, bot - top, top);
        top = fmaf(ax, tr0.z - tl0.z, tl0.z);
        bot = fmaf(ax, br0.z - bl0.z, bl0.z);
        r0.z = fmaf(ay, bot - top, top);
        top = fmaf(ax, tr0.w - tl0.w, tl0.w);
        bot = fmaf(ax, br0.w - bl0.w, bl0.w);
        r0.w = fmaf(ay, bot - top, top);

        top = fmaf(ax, tr1.x - tl1.x, tl1.x);
        bot = fmaf(ax, br1.x - bl1.x, bl1.x);
        r1.x = fmaf(ay, bot - top, top);
        top = fmaf(ax, tr1.y - tl1.y, tl1.y);
        bot = fmaf(ax, br1.y - bl1.y, bl1.y);
        r1.y = fmaf(ay, bot - top, top);
        top = fmaf(ax, tr1.z - tl1.z, tl1.z);
        bot = fmaf(ax, br1.z - bl1.z, bl1.z);
        r1.z = fmaf(ay, bot - top, top);
        top = fmaf(ax, tr1.w - tl1.w, tl1.w);
        bot = fmaf(ax, br1.w - bl1.w, bl1.w);
        r1.w = fmaf(ay, bot - top, top);
    }

    float4* o = out + ((long)p * 16 + (c8 << 1));
    stcs4(o, r0);
    stcs4(o + 1, r1);
}

extern "C" void kernel_launch(void* const* d_in, const int* in_sizes, int n_in,
                              void* d_out, int out_size)
{
    const float4* img  = (const float4*)d_in[0];
    const float2* flow = (const float2*)d_in[1];
    float4* out = (float4*)d_out;

    // out_size = 33554432 floats -> 4194304 threads (8 channels each)
    const int threads = out_size / 8;
    const int block = 256;
    const int grid = (threads + block - 1) / block;  // 16384
    warp_kernel<<<grid, block>>>(img, flow, out);
}

// round 3
// speedup vs baseline: 1.1152x; 1.1152x over previous
#include <cuda_runtime.h>
#include <cuda_bf16.h>

// dense_image_warp: out[b,y,x,c] = bilinear(image, (y,x) - flow[b,y,x])
// B=8, H=256, W=256, C=64 (fp32).
// One thread per float4 (4 channels) x 2 pixels (p and p+262144).
// All corner loads fully coalesced (16 lanes x 16B contiguous per pixel);
// 10 independent loads per thread for MLP. Streaming stores.

__device__ __forceinline__ void stcs4(float4* p, float4 v) {
    asm volatile("st.global.cs.v4.f32 [%0], {%1,%2,%3,%4};"
                 :: "l"(p), "f"(v.x), "f"(v.y), "f"(v.z), "f"(v.w) : "memory");
}

__device__ __forceinline__ float4 lerp2d(float4 tl, float4 tr, float4 bl, float4 br,
                                         float ax, float ay) {
    float4 r;
    float top, bot;
    top = fmaf(ax, tr.x - tl.x, tl.x);
    bot = fmaf(ax, br.x - bl.x, bl.x);
    r.x = fmaf(ay, bot - top, top);
    top = fmaf(ax, tr.y - tl.y, tl.y);
    bot = fmaf(ax, br.y - bl.y, bl.y);
    r.y = fmaf(ay, bot - top, top);
    top = fmaf(ax, tr.z - tl.z, tl.z);
    bot = fmaf(ax, br.z - bl.z, bl.z);
    r.z = fmaf(ay, bot - top, top);
    top = fmaf(ax, tr.w - tl.w, tl.w);
    bot = fmaf(ax, br.w - bl.w, bl.w);
    r.w = fmaf(ay, bot - top, top);
    return r;
}

__global__ __launch_bounds__(256) void warp_kernel(
    const float4* __restrict__ img,    // [B,H,W,C] as float4, pixel stride 16
    const float2* __restrict__ flow,   // [B,H,W,2] as float2, one per pixel
    float4* __restrict__ out)
{
    const int tid = blockIdx.x * blockDim.x + threadIdx.x;
    const int c4 = tid & 15;          // channel group 0..15
    const int p0 = tid >> 4;          // pixel in batches 0..3
    const int p1 = p0 + 262144;       // same (y,x) in batches 4..7

    const int x  = p0 & 255;
    const int y  = (p0 >> 8) & 255;
    const int b0 = p0 >> 16;          // 0..3

    // Two independent flow loads (broadcast across the 16-lane pixel group)
    const float2 f0 = __ldg(&flow[p0]);
    const float2 f1 = __ldg(&flow[p1]);

    // --- pixel 0 indices ---
    float qy0 = (float)y - f0.x;
    float qx0 = (float)x - f0.y;
    float fy0 = fminf(fmaxf(floorf(qy0), 0.0f), 254.0f);
    float fx0 = fminf(fmaxf(floorf(qx0), 0.0f), 254.0f);
    const float ay0 = fminf(fmaxf(qy0 - fy0, 0.0f), 1.0f);
    const float ax0 = fminf(fmaxf(qx0 - fx0, 0.0f), 1.0f);
    const long base0 = (((long)((b0 << 8) + (int)fy0) << 8) + (int)fx0) * 16 + c4;

    // --- pixel 1 indices ---
    float qy1 = (float)y - f1.x;
    float qx1 = (float)x - f1.y;
    float fy1 = fminf(fmaxf(floorf(qy1), 0.0f), 254.0f);
    float fx1 = fminf(fmaxf(floorf(qx1), 0.0f), 254.0f);
    const float ay1 = fminf(fmaxf(qy1 - fy1, 0.0f), 1.0f);
    const float ax1 = fminf(fmaxf(qx1 - fx1, 0.0f), 1.0f);
    const long base1 = (((long)(((b0 + 4) << 8) + (int)fy1) << 8) + (int)fx1) * 16 + c4;

    // 8 independent fully-coalesced 128-bit gathers
    const float4 tl0 = __ldg(img + base0);
    const float4 tr0 = __ldg(img + base0 + 16);
    const float4 bl0 = __ldg(img + base0 + 16 * 256);
    const float4 br0 = __ldg(img + base0 + 16 * 256 + 16);
    const float4 tl1 = __ldg(img + base1);
    const float4 tr1 = __ldg(img + base1 + 16);
    const float4 bl1 = __ldg(img + base1 + 16 * 256);
    const float4 br1 = __ldg(img + base1 + 16 * 256 + 16);

    const float4 r0 = lerp2d(tl0, tr0, bl0, br0, ax0, ay0);
    const float4 r1 = lerp2d(tl1, tr1, bl1, br1, ax1, ay1);

    stcs4(out + tid, r0);
    stcs4(out + tid + 4194304, r1);   // p1*16 + c4 = tid + 262144*16
}

extern "C" void kernel_launch(void* const* d_in, const int* in_sizes, int n_in,
                              void* d_out, int out_size)
{
    const float4* img  = (const float4*)d_in[0];
    const float2* flow = (const float2*)d_in[1];
    float4* out = (float4*)d_out;

    // out_size = 33554432 floats -> 8388608 float4 -> 4194304 threads (2 px each)
    const int threads = out_size / 8;
    const int block = 256;
    const int grid = (threads + block - 1) / block;  // 16384
    warp_kernel<<<grid, block>>>(img, flow, out);
}

// round 4
// speedup vs baseline: 1.1531x; 1.0339x over previous
#include <cuda_runtime.h>
#include <cuda_bf16.h>

// dense_image_warp: out[b,y,x,c] = bilinear(image, (y,x) - flow[b,y,x])
// B=8, H=256, W=256, C=64 (fp32).
// One thread per float4 (4 channels) x 2 pixels (batches 0-3 and 4-7).
// Fully coalesced corner gathers; 32-bit addressing; block=128 for
// fine-grained scheduling / high achieved occupancy. Streaming stores.

__device__ __forceinline__ void stcs4(float4* p, float4 v) {
    asm volatile("st.global.cs.v4.f32 [%0], {%1,%2,%3,%4};"
                 :: "l"(p), "f"(v.x), "f"(v.y), "f"(v.z), "f"(v.w) : "memory");
}

__device__ __forceinline__ float4 lerp2d(float4 tl, float4 tr, float4 bl, float4 br,
                                         float ax, float ay) {
    float4 r;
    float top, bot;
    top = fmaf(ax, tr.x - tl.x, tl.x);
    bot = fmaf(ax, br.x - bl.x, bl.x);
    r.x = fmaf(ay, bot - top, top);
    top = fmaf(ax, tr.y - tl.y, tl.y);
    bot = fmaf(ax, br.y - bl.y, bl.y);
    r.y = fmaf(ay, bot - top, top);
    top = fmaf(ax, tr.z - tl.z, tl.z);
    bot = fmaf(ax, br.z - bl.z, bl.z);
    r.z = fmaf(ay, bot - top, top);
    top = fmaf(ax, tr.w - tl.w, tl.w);
    bot = fmaf(ax, br.w - bl.w, bl.w);
    r.w = fmaf(ay, bot - top, top);
    return r;
}

__global__ __launch_bounds__(128) void warp_kernel(
    const float4* __restrict__ img,    // [B,H,W,C] as float4, pixel stride 16
    const float2* __restrict__ flow,   // [B,H,W,2] as float2, one per pixel
    float4* __restrict__ out)
{
    const int tid = blockIdx.x * blockDim.x + threadIdx.x;
    const int c4 = tid & 15;          // channel group 0..15
    const int p0 = tid >> 4;          // pixel in batches 0..3
    const int p1 = p0 + 262144;       // same (y,x) in batches 4..7

    const int x  = p0 & 255;
    const int y  = (p0 >> 8) & 255;
    const int b0 = p0 >> 16;          // 0..3

    const float2 f0 = __ldg(&flow[p0]);
    const float2 f1 = __ldg(&flow[p1]);

    // --- pixel 0 ---
    float qy0 = (float)y - f0.x;
    float qx0 = (float)x - f0.y;
    float fy0 = fminf(fmaxf(floorf(qy0), 0.0f), 254.0f);
    float fx0 = fminf(fmaxf(floorf(qx0), 0.0f), 254.0f);
    const float ay0 = fminf(fmaxf(qy0 - fy0, 0.0f), 1.0f);
    const float ax0 = fminf(fmaxf(qx0 - fx0, 0.0f), 1.0f);
    // base in float4 units (fits in int32: max 8*256*256*16 = 16.7M)
    const int base0 = ((((b0 << 8) + (int)fy0) << 8) + (int)fx0) * 16 + c4;

    // --- pixel 1 ---
    float qy1 = (float)y - f1.x;
    float qx1 = (float)x - f1.y;
    float fy1 = fminf(fmaxf(floorf(qy1), 0.0f), 254.0f);
    float fx1 = fminf(fmaxf(floorf(qx1), 0.0f), 254.0f);
    const float ay1 = fminf(fmaxf(qy1 - fy1, 0.0f), 1.0f);
    const float ax1 = fminf(fmaxf(qx1 - fx1, 0.0f), 1.0f);
    const int base1 = ((((b0 + 4) << 8) + (int)fy1 << 8) + (int)fx1) * 16 + c4;

    // 8 independent fully-coalesced 128-bit gathers
    const float4 tl0 = __ldg(img + base0);
    const float4 tr0 = __ldg(img + base0 + 16);
    const float4 bl0 = __ldg(img + base0 + 16 * 256);
    const float4 br0 = __ldg(img + base0 + 16 * 256 + 16);
    const float4 tl1 = __ldg(img + base1);
    const float4 tr1 = __ldg(img + base1 + 16);
    const float4 bl1 = __ldg(img + base1 + 16 * 256);
    const float4 br1 = __ldg(img + base1 + 16 * 256 + 16);

    const float4 r0 = lerp2d(tl0, tr0, bl0, br0, ax0, ay0);
    const float4 r1 = lerp2d(tl1, tr1, bl1, br1, ax1, ay1);

    stcs4(out + tid, r0);
    stcs4(out + tid + 4194304, r1);   // p1*16 + c4
}

extern "C" void kernel_launch(void* const* d_in, const int* in_sizes, int n_in,
                              void* d_out, int out_size)
{
    const float4* img  = (const float4*)d_in[0];
    const float2* flow = (const float2*)d_in[1];
    float4* out = (float4*)d_out;

    // out_size = 33554432 floats -> 4194304 threads (2 pixels each)
    const int threads = out_size / 8;
    const int block = 128;
    const int grid = (threads + block - 1) / block;  // 32768
    warp_kernel<<<grid, block>>>(img, flow, out);
}

// round 5
// speedup vs baseline: 1.2070x; 1.0468x over previous
#include <cuda_runtime.h>
#include <cuda_bf16.h>

// dense_image_warp: out[b,y,x,c] = bilinear(image, (y,x) - flow[b,y,x])
// B=8, H=256, W=256, C=64 (fp32).
// One thread per float4 (4 channels) at one (y,x), looping over all 8 batches
// (4 iterations x 2 pixels). Next iteration's flow is prefetched while the
// current iteration's 8 gathers are in flight -> no serial flow-wait phase.

__device__ __forceinline__ void stcs4(float4* p, float4 v) {
    asm volatile("st.global.cs.v4.f32 [%0], {%1,%2,%3,%4};"
                 :: "l"(p), "f"(v.x), "f"(v.y), "f"(v.z), "f"(v.w) : "memory");
}

__device__ __forceinline__ float4 lerp2d(float4 tl, float4 tr, float4 bl, float4 br,
                                         float ax, float ay) {
    float4 r;
    float top, bot;
    top = fmaf(ax, tr.x - tl.x, tl.x);
    bot = fmaf(ax, br.x - bl.x, bl.x);
    r.x = fmaf(ay, bot - top, top);
    top = fmaf(ax, tr.y - tl.y, tl.y);
    bot = fmaf(ax, br.y - bl.y, bl.y);
    r.y = fmaf(ay, bot - top, top);
    top = fmaf(ax, tr.z - tl.z, tl.z);
    bot = fmaf(ax, br.z - bl.z, bl.z);
    r.z = fmaf(ay, bot - top, top);
    top = fmaf(ax, tr.w - tl.w, tl.w);
    bot = fmaf(ax, br.w - bl.w, bl.w);
    r.w = fmaf(ay, bot - top, top);
    return r;
}

// Compute image base (in float4 units) + weights for query (y,x) - f in batch b.
__device__ __forceinline__ int mkbase(int b, int y, int x, int c4, float2 f,
                                      float& ax, float& ay) {
    const float qy = (float)y - f.x;
    const float qx = (float)x - f.y;
    const float fy = fminf(fmaxf(floorf(qy), 0.0f), 254.0f);
    const float fx = fminf(fmaxf(floorf(qx), 0.0f), 254.0f);
    ay = fminf(fmaxf(qy - fy, 0.0f), 1.0f);
    ax = fminf(fmaxf(qx - fx, 0.0f), 1.0f);
    return ((((b << 8) + (int)fy) << 8) + (int)fx) * 16 + c4;
}

__global__ __launch_bounds__(128) void warp_kernel(
    const float4* __restrict__ img,    // [B,H,W,C] as float4, pixel stride 16
    const float2* __restrict__ flow,   // [B,H,W,2] as float2, one per pixel
    float4* __restrict__ out)
{
    const int tid = blockIdx.x * blockDim.x + threadIdx.x;  // 0..2^20-1
    const int c4 = tid & 15;          // channel group 0..15
    const int p  = tid >> 4;          // (y,x) pixel index 0..65535
    const int x  = p & 255;
    const int y  = p >> 8;

    // Prologue: flow for batches 0 and 4
    float2 f0 = __ldg(&flow[p]);
    float2 f1 = __ldg(&flow[p + 4 * 65536]);

    #pragma unroll
    for (int it = 0; it < 4; ++it) {
        // This iteration handles batches it and it+4.
        float ax0, ay0, ax1, ay1;
        const int base0 = mkbase(it,     y, x, c4, f0, ax0, ay0);
        const int base1 = mkbase(it + 4, y, x, c4, f1, ax1, ay1);

        // 8 independent fully-coalesced 128-bit gathers
        const float4 tl0 = __ldg(img + base0);
        const float4 tr0 = __ldg(img + base0 + 16);
        const float4 bl0 = __ldg(img + base0 + 16 * 256);
        const float4 br0 = __ldg(img + base0 + 16 * 256 + 16);
        const float4 tl1 = __ldg(img + base1);
        const float4 tr1 = __ldg(img + base1 + 16);
        const float4 bl1 = __ldg(img + base1 + 16 * 256);
        const float4 br1 = __ldg(img + base1 + 16 * 256 + 16);

        // Prefetch next iteration's flow while gathers are in flight
        if (it < 3) {
            f0 = __ldg(&flow[p + (it + 1) * 65536]);
            f1 = __ldg(&flow[p + (it + 5) * 65536]);
        }

        const float4 r0 = lerp2d(tl0, tr0, bl0, br0, ax0, ay0);
        const float4 r1 = lerp2d(tl1, tr1, bl1, br1, ax1, ay1);

        // out offset (float4): (b*65536 + p)*16 + c4 = tid + b*1048576
        stcs4(out + tid + it * 1048576, r0);
        stcs4(out + tid + (it + 4) * 1048576, r1);
    }
}

extern "C" void kernel_launch(void* const* d_in, const int* in_sizes, int n_in,
                              void* d_out, int out_size)
{
    const float4* img  = (const float4*)d_in[0];
    const float2* flow = (const float2*)d_in[1];
    float4* out = (float4*)d_out;

    // 65536 (y,x) pixels * 16 channel-groups = 1048576 threads, 8 pixels each
    const int threads = 1 << 20;
    const int block = 128;
    const int grid = threads / block;  // 8192
    warp_kernel<<<grid, block>>>(img, flow, out);
}

// round 6
// speedup vs baseline: 1.2085x; 1.0012x over previous
#include <cuda_runtime.h>
#include <cuda_bf16.h>

// dense_image_warp: out[b,y,x,c] = bilinear(image, (y,x) - flow[b,y,x])
// B=8, H=256, W=256, C=64 (fp32).
// One thread per float4 (4 channels) at one (y,x), over all 8 batches
// (4 iterations x 2 pixels). Two-deep software pipeline: iteration i+1's
// 8 gathers are issued before iteration i's lerp, so ~16 gathers are in
// flight per warp continuously (no dead compute phase).

__device__ __forceinline__ void stcs4(float4* p, float4 v) {
    asm volatile("st.global.cs.v4.f32 [%0], {%1,%2,%3,%4};"
                 :: "l"(p), "f"(v.x), "f"(v.y), "f"(v.z), "f"(v.w) : "memory");
}

__device__ __forceinline__ float4 lerp2d(float4 tl, float4 tr, float4 bl, float4 br,
                                         float ax, float ay) {
    float4 r;
    float top, bot;
    top = fmaf(ax, tr.x - tl.x, tl.x);
    bot = fmaf(ax, br.x - bl.x, bl.x);
    r.x = fmaf(ay, bot - top, top);
    top = fmaf(ax, tr.y - tl.y, tl.y);
    bot = fmaf(ax, br.y - bl.y, bl.y);
    r.y = fmaf(ay, bot - top, top);
    top = fmaf(ax, tr.z - tl.z, tl.z);
    bot = fmaf(ax, br.z - bl.z, bl.z);
    r.z = fmaf(ay, bot - top, top);
    top = fmaf(ax, tr.w - tl.w, tl.w);
    bot = fmaf(ax, br.w - bl.w, bl.w);
    r.w = fmaf(ay, bot - top, top);
    return r;
}

// Compute image base (float4 units) + weights for query (y,x)-f in batch b.
__device__ __forceinline__ int mkbase(int b, int y, int x, int c4, float2 f,
                                      float& ax, float& ay) {
    const float qy = (float)y - f.x;
    const float qx = (float)x - f.y;
    const float fy = fminf(fmaxf(floorf(qy), 0.0f), 254.0f);
    const float fx = fminf(fmaxf(floorf(qx), 0.0f), 254.0f);
    ay = fminf(fmaxf(qy - fy, 0.0f), 1.0f);
    ax = fminf(fmaxf(qx - fx, 0.0f), 1.0f);
    return ((((b << 8) + (int)fy) << 8) + (int)fx) * 16 + c4;
}

struct Gath {
    float4 tl0, tr0, bl0, br0, tl1, tr1, bl1, br1;
    float ax0, ay0, ax1, ay1;
};

__device__ __forceinline__ void issue_gathers(const float4* __restrict__ img,
                                              int base0, int base1,
                                              Gath& g) {
    g.tl0 = __ldg(img + base0);
    g.tr0 = __ldg(img + base0 + 16);
    g.bl0 = __ldg(img + base0 + 16 * 256);
    g.br0 = __ldg(img + base0 + 16 * 256 + 16);
    g.tl1 = __ldg(img + base1);
    g.tr1 = __ldg(img + base1 + 16);
    g.bl1 = __ldg(img + base1 + 16 * 256);
    g.br1 = __ldg(img + base1 + 16 * 256 + 16);
}

__global__ __launch_bounds__(128) void warp_kernel(
    const float4* __restrict__ img,    // [B,H,W,C] as float4, pixel stride 16
    const float2* __restrict__ flow,   // [B,H,W,2] as float2, one per pixel
    float4* __restrict__ out)
{
    const int tid = blockIdx.x * blockDim.x + threadIdx.x;  // 0..2^20-1
    const int c4 = tid & 15;          // channel group 0..15
    const int p  = tid >> 4;          // (y,x) pixel index 0..65535
    const int x  = p & 255;
    const int y  = p >> 8;

    Gath g[4];

    // Prologue: flow + gathers for iteration 0 (batches 0, 4)
    float2 f0 = __ldg(&flow[p]);
    float2 f1 = __ldg(&flow[p + 4 * 65536]);
    {
        int b0 = mkbase(0, y, x, c4, f0, g[0].ax0, g[0].ay0);
        int b1 = mkbase(4, y, x, c4, f1, g[0].ax1, g[0].ay1);
        issue_gathers(img, b0, b1, g[0]);
    }
    f0 = __ldg(&flow[p + 1 * 65536]);
    f1 = __ldg(&flow[p + 5 * 65536]);

    #pragma unroll
    for (int it = 0; it < 4; ++it) {
        // Issue iteration it+1's gathers BEFORE consuming iteration it's data.
        if (it < 3) {
            int b0 = mkbase(it + 1, y, x, c4, f0, g[it + 1].ax0, g[it + 1].ay0);
            int b1 = mkbase(it + 5, y, x, c4, f1, g[it + 1].ax1, g[it + 1].ay1);
            issue_gathers(img, b0, b1, g[it + 1]);
            if (it < 2) {
                f0 = __ldg(&flow[p + (it + 2) * 65536]);
                f1 = __ldg(&flow[p + (it + 6) * 65536]);
            }
        }

        // Consume iteration it (first use of its gather results).
        const float4 r0 = lerp2d(g[it].tl0, g[it].tr0, g[it].bl0, g[it].br0,
                                 g[it].ax0, g[it].ay0);
        const float4 r1 = lerp2d(g[it].tl1, g[it].tr1, g[it].bl1, g[it].br1,
                                 g[it].ax1, g[it].ay1);

        stcs4(out + tid + it * 1048576, r0);
        stcs4(out + tid + (it + 4) * 1048576, r1);
    }
}

extern "C" void kernel_launch(void* const* d_in, const int* in_sizes, int n_in,
                              void* d_out, int out_size)
{
    const float4* img  = (const float4*)d_in[0];
    const float2* flow = (const float2*)d_in[1];
    float4* out = (float4*)d_out;

    // 65536 (y,x) pixels * 16 channel-groups = 1048576 threads, 8 pixels each
    const int threads = 1 << 20;
    const int block = 128;
    const int grid = threads / block;  // 8192
    warp_kernel<<<grid, block>>>(img, flow, out);
}